// round 15
// baseline (speedup 1.0000x reference)
#include <cuda_runtime.h>
#include <cuda_fp16.h>
#include <cstdint>

// Problem constants
#define Nn 20000
#define Ee 320000
#define Bb 2
#define INF_DIM 32
#define HIDD 64
#define HEADS 4
#define OUTD 8
#define SLOPE 0.2f

#define NB (Nn*Bb)              // 40000
#define FTC (HEADS*HIDD)        // 256

// Scratch (device globals)
__device__ __align__(16) float g_x[NB*HIDD];
__device__ __align__(16) __half g_fth[(size_t)NB*FTC];   // ft in fp16
__device__ __align__(16) float g_res[NB*HIDD];
__device__ float g_el[NB*HEADS];   // [(node*2+b)*4 + h]
__device__ float g_er[NB*HEADS];
__device__ float g_P[HIDD*8];      // [k*8 + q], q<4: Pl, q>=4: Pr
// round-1 combined (encoder-folded) weights
__device__ __align__(16) float g_Wg1[INF_DIM*FTC];
__device__ float g_bg1[FTC];
__device__ __align__(16) float g_Wr1[INF_DIM*HIDD];
__device__ float g_br1[HIDD];
__device__ float g_P1[INF_DIM*8];
__device__ float g_bp1[8];
__device__ float g_zeros[FTC];     // never written: stays zero
__device__ int g_deg[Nn];
__device__ int g_rowptr[Nn];
__device__ int g_col[Ee];
__device__ int g_rank[Ee];
__device__ int g_total;

// ---- packed f32x2 helpers (sm_103a FFMA2) ----
__device__ __forceinline__ uint64_t pk2(float lo, float hi) {
    uint64_t r; asm("mov.b64 %0, {%1,%2};" : "=l"(r) : "f"(lo), "f"(hi)); return r;
}
__device__ __forceinline__ void fma2(uint64_t& acc, uint64_t a, uint64_t b) {
    asm("fma.rn.f32x2 %0, %1, %2, %0;" : "+l"(acc) : "l"(a), "l"(b));
}
__device__ __forceinline__ float2 upk(uint64_t v) {
    float2 r; asm("mov.b64 {%0,%1}, %2;" : "=f"(r.x), "=f"(r.y) : "l"(v)); return r;
}

// ---------------- setup: zero CSR counters + proj P + combined round-1 weights ----------------
// blocks 0..78: zero g_deg / g_total. block 79: P = reshape(W_gat)@a, then
// Wg1 = W_enc@W_gat, bg1 = b_enc@W_gat, Wr1 = W_enc@W_res, br1 = b_enc@W_res+b_res,
// P1 = W_enc@P, bp1 = b_enc@P.
__global__ void setup_k(const float* __restrict__ W_enc, const float* __restrict__ b_enc,
                        const float* __restrict__ W_gat, const float* __restrict__ W_res,
                        const float* __restrict__ b_res,
                        const float* __restrict__ a_l, const float* __restrict__ a_r) {
    int t = threadIdx.x;
    if (blockIdx.x < 79) {
        int idx = blockIdx.x * 256 + t;
        if (idx < Nn) g_deg[idx] = 0;
        if (idx == 0) g_total = 0;
        return;
    }
    __shared__ float Psh[HIDD*8];
    // proj: 512 outputs
    for (int i = t; i < HIDD*8; i += 256) {
        int k = i >> 3, q = i & 7;
        int h = q & 3;
        const float* a = (q < 4) ? a_l : a_r;
        float s = 0.f;
#pragma unroll
        for (int d = 0; d < HIDD; d++)
            s += W_gat[k*FTC + h*HIDD + d] * a[h*HIDD + d];
        Psh[i] = s;
        g_P[i] = s;
    }
    __syncthreads();
    // comb: 10824 outputs
    for (int idx = t; idx < 10824; idx += 256) {
        if (idx < 8192) {                       // Wg1[in][c]
            int in = idx >> 8, c = idx & 255;
            float s = 0.f;
#pragma unroll
            for (int k = 0; k < HIDD; k++) s += W_enc[in*HIDD + k] * W_gat[k*FTC + c];
            g_Wg1[in*FTC + c] = s;
        } else if (idx < 8448) {                // bg1[c]
            int c = idx - 8192;
            float s = 0.f;
#pragma unroll
            for (int k = 0; k < HIDD; k++) s += b_enc[k] * W_gat[k*FTC + c];
            g_bg1[c] = s;
        } else if (idx < 10496) {               // Wr1[in][c]
            int j = idx - 8448;
            int in = j >> 6, c = j & 63;
            float s = 0.f;
#pragma unroll
            for (int k = 0; k < HIDD; k++) s += W_enc[in*HIDD + k] * W_res[k*HIDD + c];
            g_Wr1[in*HIDD + c] = s;
        } else if (idx < 10560) {               // br1[c]
            int c = idx - 10496;
            float s = b_res[c];
#pragma unroll
            for (int k = 0; k < HIDD; k++) s += b_enc[k] * W_res[k*HIDD + c];
            g_br1[c] = s;
        } else if (idx < 10816) {               // P1[in][q]
            int j = idx - 10560;
            int in = j >> 3, q = j & 7;
            float s = 0.f;
#pragma unroll
            for (int k = 0; k < HIDD; k++) s += W_enc[in*HIDD + k] * Psh[k*8 + q];
            g_P1[in*8 + q] = s;
        } else {                                // bp1[q]
            int q = idx - 10816;
            float s = 0.f;
#pragma unroll
            for (int k = 0; k < HIDD; k++) s += b_enc[k] * Psh[k*8 + q];
            g_bp1[q] = s;
        }
    }
}

// ---------------- CSR build ----------------
__global__ void hist_k(const int* __restrict__ ei) {
    int idx = blockIdx.x * blockDim.x + threadIdx.x;
    if (idx < Ee) g_rank[idx] = atomicAdd(&g_deg[ei[Ee + idx]], 1);
}

__global__ void alloc_k() {
    int idx = blockIdx.x * blockDim.x + threadIdx.x;
    int lane = threadIdx.x & 31;
    int d = (idx < Nn) ? g_deg[idx] : 0;
    int incl = d;
#pragma unroll
    for (int o = 1; o < 32; o <<= 1) {
        int t = __shfl_up_sync(0xffffffffu, incl, o);
        if (lane >= o) incl += t;
    }
    int wtot = __shfl_sync(0xffffffffu, incl, 31);
    int base = 0;
    if (lane == 0) base = atomicAdd(&g_total, wtot);
    base = __shfl_sync(0xffffffffu, base, 0);
    if (idx < Nn) g_rowptr[idx] = base + incl - d;
}

__global__ void fill_k(const int* __restrict__ ei) {
    int idx = blockIdx.x * blockDim.x + threadIdx.x;
    if (idx >= Ee) return;
    int d = ei[Ee + idx];
    g_col[g_rowptr[d] + g_rank[idx]] = ei[idx];
}

// ---------------- ft/res/el/er from either h (round 1, K=32) or g_x (round 2, K=64) ----------------
#define FTROWS 32
#define XPAD 17             // u64 pitch (pad)
__global__ void ft_k(const float* __restrict__ h,
                     const float* __restrict__ W_gat,
                     const float* __restrict__ W_res, const float* __restrict__ b_res,
                     int round1) {
    __shared__ uint64_t xs2[HIDD * XPAD];
    __shared__ float Ps[HIDD * 8];
    int t = threadIdx.x;
    int nb0 = blockIdx.x * FTROWS;

    const float* Wg = round1 ? g_Wg1 : W_gat;
    const float* bg = round1 ? g_bg1 : g_zeros;
    const float* Wr = round1 ? g_Wr1 : W_res;
    const float* br = round1 ? g_br1 : b_res;
    const float* Pm = round1 ? g_P1  : g_P;
    const float* bp = round1 ? g_bp1 : g_zeros;
    const int K = round1 ? INF_DIM : HIDD;

    // load source transposed row-paired into smem
    {
        float* xf = (float*)xs2;
        if (round1) {
            for (int i = t; i < FTROWS*INF_DIM; i += 256) {
                int row = i >> 5, k = i & 31;
                int nbrow = nb0 + row;
                int n = nbrow >> 1, b = nbrow & 1;
                xf[k*(2*XPAD) + row] = h[((size_t)b*Nn + n)*INF_DIM + k];
            }
        } else {
            for (int i = t; i < FTROWS*HIDD; i += 256) {
                int row = i >> 6, k = i & 63;
                xf[k*(2*XPAD) + row] = g_x[(size_t)(nb0 + row)*HIDD + k];
            }
        }
        for (int i = t; i < K*8; i += 256) Ps[i] = Pm[i];
    }
    __syncthreads();

    // main GEMM: col-quad x 4 row-pairs (1 LDG.128 + 4 LDS.64 + 16 FFMA2 per k)
    {
        int cq = t & 63;
        int rh = t >> 6;
        uint64_t acc[4][4];
#pragma unroll
        for (int c = 0; c < 4; c++) {
            float bc = bg[cq*4 + c];
            uint64_t b2 = pk2(bc, bc);
#pragma unroll
            for (int r = 0; r < 4; r++) acc[c][r] = b2;
        }

        for (int k = 0; k < K; k++) {
            float4 w = *(const float4*)&Wg[k*FTC + cq*4];
            uint64_t w0 = pk2(w.x, w.x);
            uint64_t w1 = pk2(w.y, w.y);
            uint64_t w2 = pk2(w.z, w.z);
            uint64_t w3 = pk2(w.w, w.w);
            const uint64_t* xr = &xs2[k*XPAD + rh*4];
#pragma unroll
            for (int r = 0; r < 4; r++) {
                uint64_t xv = xr[r];
                fma2(acc[0][r], xv, w0);
                fma2(acc[1][r], xv, w1);
                fma2(acc[2][r], xv, w2);
                fma2(acc[3][r], xv, w3);
            }
        }
#pragma unroll
        for (int r = 0; r < 4; r++) {
            float2 v0 = upk(acc[0][r]);
            float2 v1 = upk(acc[1][r]);
            float2 v2 = upk(acc[2][r]);
            float2 v3 = upk(acc[3][r]);
            int rp = rh*4 + r;
            __half2 e0 = __floats2half2_rn(v0.x, v1.x);
            __half2 e1 = __floats2half2_rn(v2.x, v3.x);
            __half2 o0 = __floats2half2_rn(v0.y, v1.y);
            __half2 o1 = __floats2half2_rn(v2.y, v3.y);
            *(uint2*)&g_fth[((size_t)(nb0 + 2*rp))*FTC + cq*4]     = make_uint2(
                *(unsigned*)&e0, *(unsigned*)&e1);
            *(uint2*)&g_fth[((size_t)(nb0 + 2*rp + 1))*FTC + cq*4] = make_uint2(
                *(unsigned*)&o0, *(unsigned*)&o1);
        }
    }

    // res: thread owns col pair (2cr, 2cr+1), 2 row-pairs
    {
        int cr = t & 31;
        int rr = t >> 5;
        float2 bb = *(const float2*)&br[cr*2];
        uint64_t a0[2], a1[2];
        a0[0] = pk2(bb.x, bb.x); a0[1] = a0[0];
        a1[0] = pk2(bb.y, bb.y); a1[1] = a1[0];
        for (int k = 0; k < K; k++) {
            float2 w = *(const float2*)&Wr[k*HIDD + cr*2];
            uint64_t w0 = pk2(w.x, w.x);
            uint64_t w1 = pk2(w.y, w.y);
            const uint64_t* xr = &xs2[k*XPAD + rr*2];
            fma2(a0[0], xr[0], w0); fma2(a1[0], xr[0], w1);
            fma2(a0[1], xr[1], w0); fma2(a1[1], xr[1], w1);
        }
#pragma unroll
        for (int i = 0; i < 2; i++) {
            float2 va = upk(a0[i]);
            float2 vb = upk(a1[i]);
            int rp = rr*2 + i;
            *(float2*)&g_res[(size_t)(nb0 + 2*rp)*HIDD + cr*2]     = make_float2(va.x, vb.x);
            *(float2*)&g_res[(size_t)(nb0 + 2*rp + 1)*HIDD + cr*2] = make_float2(va.y, vb.y);
        }
    }

    // el/er
    {
        int r = t >> 3, q = t & 7;
        const float* xf = (const float*)xs2;
        float s = bp[q];
        for (int k = 0; k < K; k++)
            s += xf[k*(2*XPAD) + r] * Ps[k*8 + q];
        int nb = nb0 + r;
        if (q < 4) g_el[nb*4 + q]       = s;
        else       g_er[nb*4 + (q - 4)] = s;
    }
}

// ---------------- fused node-centric GAT aggregation + update (+ optional decoder) ----------------
// EXACT R11 structure (best known): one warp per dst node, both batches;
// e-values batched per 32-edge window; simple per-edge break in the FMA loop.
__global__ void node_agg_k(const float* __restrict__ b_gat,
                           const float* __restrict__ W_dec, const float* __restrict__ b_dec,
                           float* __restrict__ out, int last) {
    int w = (blockIdx.x * blockDim.x + threadIdx.x) >> 5;
    int lane = threadIdx.x & 31;
    if (w >= Nn) return;
    int beg = g_rowptr[w];
    int end = beg + g_deg[w];

    int slot = lane >> 3;              // e-role: edge sub-slot (0..3)
    int bh   = lane & 7;               // e-role: (b,h)
    int b    = lane >> 4;              // gather role: batch
    int l16  = lane & 15;              // gather role: dim-quad

    float er_v = (lane < 8) ? g_er[w*8 + lane] : 0.f;
    float er_mine = __shfl_sync(0xffffffffu, er_v, bh);

    float zpart = 0.f;
    float4 acc[HEADS];
#pragma unroll
    for (int h = 0; h < HEADS; h++) acc[h] = make_float4(0.f, 0.f, 0.f, 0.f);

    for (int i0 = beg; i0 < end; i0 += 32) {
        int nE = end - i0; if (nE > 32) nE = 32;
        int sj = (i0 + lane < end) ? g_col[i0 + lane] : 0;

        // batch e-values: lane handles edges j = slot + 4k, its own bh
        float ereg[8];
#pragma unroll
        for (int k = 0; k < 8; k++) {
            int j = slot + 4*k;
            int s = __shfl_sync(0xffffffffu, sj, j);
            float e = 0.f;
            if (j < nE) {
                float v = g_el[s*8 + bh] + er_mine;
                v = v > 0.f ? v : SLOPE * v;
                e = __expf(v);
            }
            ereg[k] = e;
            zpart += e;
        }

        // FMA loop: pure shfl + coalesced fp16 gather + FMA
#pragma unroll
        for (int j = 0; j < 32; j++) {
            if (j >= nE) break;
            const int kk = j >> 2, sl2 = j & 3;
            int s = __shfl_sync(0xffffffffu, sj, j);
            float a0 = __shfl_sync(0xffffffffu, ereg[kk], sl2*8 + b*4 + 0);
            float a1 = __shfl_sync(0xffffffffu, ereg[kk], sl2*8 + b*4 + 1);
            float a2 = __shfl_sync(0xffffffffu, ereg[kk], sl2*8 + b*4 + 2);
            float a3 = __shfl_sync(0xffffffffu, ereg[kk], sl2*8 + b*4 + 3);
            const uint2* f = (const uint2*)&g_fth[((size_t)(s*2 + b))*FTC];
            uint2 u0 = f[l16];
            uint2 u1 = f[16 + l16];
            uint2 u2 = f[32 + l16];
            uint2 u3 = f[48 + l16];
            float2 p, q;
            p = __half22float2(*(__half2*)&u0.x); q = __half22float2(*(__half2*)&u0.y);
            acc[0].x += a0*p.x; acc[0].y += a0*p.y; acc[0].z += a0*q.x; acc[0].w += a0*q.y;
            p = __half22float2(*(__half2*)&u1.x); q = __half22float2(*(__half2*)&u1.y);
            acc[1].x += a1*p.x; acc[1].y += a1*p.y; acc[1].z += a1*q.x; acc[1].w += a1*q.y;
            p = __half22float2(*(__half2*)&u2.x); q = __half22float2(*(__half2*)&u2.y);
            acc[2].x += a2*p.x; acc[2].y += a2*p.y; acc[2].z += a2*q.x; acc[2].w += a2*q.y;
            p = __half22float2(*(__half2*)&u3.x); q = __half22float2(*(__half2*)&u3.y);
            acc[3].x += a3*p.x; acc[3].y += a3*p.y; acc[3].z += a3*q.x; acc[3].w += a3*q.y;
        }
    }

    // z reduce: sum over the 4 edge sub-slots -> lane holds z for its bh
    zpart += __shfl_xor_sync(0xffffffffu, zpart, 8);
    zpart += __shfl_xor_sync(0xffffffffu, zpart, 16);

    // normalize + head-mean
    float4 o = make_float4(0.f, 0.f, 0.f, 0.f);
#pragma unroll
    for (int h = 0; h < HEADS; h++) {
        float zh = __shfl_sync(0xffffffffu, zpart, b*4 + h);
        float rz = (zh > 0.f) ? 0.25f / zh : 0.f;
        o.x += acc[h].x * rz; o.y += acc[h].y * rz;
        o.z += acc[h].z * rz; o.w += acc[h].w * rz;
    }

    // epilogue: + mean_h(b_gat) + res, ELU
    int d0 = l16 * 4;
    const float4* bg = (const float4*)b_gat;
    float4 b0 = bg[l16], b1 = bg[16 + l16], b2 = bg[32 + l16], b3 = bg[48 + l16];
    float4 bgm;
    bgm.x = 0.25f*(b0.x + b1.x + b2.x + b3.x);
    bgm.y = 0.25f*(b0.y + b1.y + b2.y + b3.y);
    bgm.z = 0.25f*(b0.z + b1.z + b2.z + b3.z);
    bgm.w = 0.25f*(b0.w + b1.w + b2.w + b3.w);

    float4 rv = *(const float4*)&g_res[((size_t)(w*2 + b))*HIDD + d0];
    float ox = o.x + bgm.x + rv.x;
    float oy = o.y + bgm.y + rv.y;
    float oz = o.z + bgm.z + rv.z;
    float ow = o.w + bgm.w + rv.w;
    ox = ox > 0.f ? ox : expm1f(ox);
    oy = oy > 0.f ? oy : expm1f(oy);
    oz = oz > 0.f ? oz : expm1f(oz);
    ow = ow > 0.f ? ow : expm1f(ow);

    if (!last) {
        *(float4*)&g_x[((size_t)(w*2 + b))*HIDD + d0] = make_float4(ox, oy, oz, ow);
    } else {
        // fused decoder: out[b, w, :] = x[w, b, :] @ W_dec + b_dec
        float po[OUTD];
        const float4* W0 = (const float4*)&W_dec[(d0 + 0)*OUTD];
        const float4* W1 = (const float4*)&W_dec[(d0 + 1)*OUTD];
        const float4* W2 = (const float4*)&W_dec[(d0 + 2)*OUTD];
        const float4* W3 = (const float4*)&W_dec[(d0 + 3)*OUTD];
        float4 wa, wb;
        wa = W0[0]; wb = W0[1];
        po[0] = ox*wa.x; po[1] = ox*wa.y; po[2] = ox*wa.z; po[3] = ox*wa.w;
        po[4] = ox*wb.x; po[5] = ox*wb.y; po[6] = ox*wb.z; po[7] = ox*wb.w;
        wa = W1[0]; wb = W1[1];
        po[0] += oy*wa.x; po[1] += oy*wa.y; po[2] += oy*wa.z; po[3] += oy*wa.w;
        po[4] += oy*wb.x; po[5] += oy*wb.y; po[6] += oy*wb.z; po[7] += oy*wb.w;
        wa = W2[0]; wb = W2[1];
        po[0] += oz*wa.x; po[1] += oz*wa.y; po[2] += oz*wa.z; po[3] += oz*wa.w;
        po[4] += oz*wb.x; po[5] += oz*wb.y; po[6] += oz*wb.z; po[7] += oz*wb.w;
        wa = W3[0]; wb = W3[1];
        po[0] += ow*wa.x; po[1] += ow*wa.y; po[2] += ow*wa.z; po[3] += ow*wa.w;
        po[4] += ow*wb.x; po[5] += ow*wb.y; po[6] += ow*wb.z; po[7] += ow*wb.w;
#pragma unroll
        for (int off = 1; off < 16; off <<= 1)
#pragma unroll
            for (int oo = 0; oo < OUTD; oo++)
                po[oo] += __shfl_xor_sync(0xffffffffu, po[oo], off);
        if (l16 == 0) {
            float* op = &out[((size_t)b*Nn + w)*OUTD];
            float4 v0 = make_float4(po[0] + b_dec[0], po[1] + b_dec[1],
                                    po[2] + b_dec[2], po[3] + b_dec[3]);
            float4 v1 = make_float4(po[4] + b_dec[4], po[5] + b_dec[5],
                                    po[6] + b_dec[6], po[7] + b_dec[7]);
            *(float4*)&op[0] = v0;
            *(float4*)&op[4] = v1;
        }
    }
}

extern "C" void kernel_launch(void* const* d_in, const int* in_sizes, int n_in,
                              void* d_out, int out_size) {
    const float* h     = (const float*)d_in[0];
    const int*   ei    = (const int*)  d_in[1];
    const float* W_enc = (const float*)d_in[2];
    const float* b_enc = (const float*)d_in[3];
    const float* W_gat = (const float*)d_in[4];
    const float* a_l   = (const float*)d_in[5];
    const float* a_r   = (const float*)d_in[6];
    const float* b_gat = (const float*)d_in[7];
    const float* W_res = (const float*)d_in[8];
    const float* b_res = (const float*)d_in[9];
    const float* W_dec = (const float*)d_in[10];
    const float* b_dec = (const float*)d_in[11];
    float* out = (float*)d_out;

    // setup: zero CSR counters + P + combined round-1 weights (one kernel)
    setup_k<<<80, 256>>>(W_enc, b_enc, W_gat, W_res, b_res, a_l, a_r);
    // CSR build
    hist_k<<<(Ee + 255)/256, 256>>>(ei);
    alloc_k<<<(Nn + 255)/256, 256>>>();
    fill_k<<<(Ee + 255)/256, 256>>>(ei);

    for (int it = 0; it < 2; ++it) {
        ft_k<<<NB/FTROWS, 256>>>(h, W_gat, W_res, b_res, it == 0);
        node_agg_k<<<(Nn*32 + 255)/256, 256>>>(b_gat, W_dec, b_dec, out, it == 1);
    }
}

// round 16
// speedup vs baseline: 1.1684x; 1.1684x over previous
#include <cuda_runtime.h>
#include <cuda_fp16.h>
#include <cstdint>

// Problem constants
#define Nn 20000
#define Ee 320000
#define Bb 2
#define INF_DIM 32
#define HIDD 64
#define HEADS 4
#define OUTD 8
#define SLOPE 0.2f

#define NB (Nn*Bb)              // 40000
#define FTC (HEADS*HIDD)        // 256

// Scratch (device globals)
__device__ __align__(16) float g_x[NB*HIDD];
__device__ __align__(16) __half g_fth[(size_t)NB*FTC];   // ft in fp16
__device__ __align__(16) float g_res[NB*HIDD];
__device__ float g_el[NB*HEADS];   // [(node*2+b)*4 + h]
__device__ float g_er[NB*HEADS];
__device__ float g_P[HIDD*8];      // [k*8 + q], q<4: Pl, q>=4: Pr
// round-1 combined (encoder-folded) weights
__device__ __align__(16) float g_Wg1[INF_DIM*FTC];
__device__ float g_bg1[FTC];
__device__ __align__(16) float g_Wr1[INF_DIM*HIDD];
__device__ float g_br1[HIDD];
__device__ float g_P1[INF_DIM*8];
__device__ float g_bp1[8];
__device__ float g_zeros[FTC];     // never written: stays zero
__device__ int g_deg[Nn];
__device__ int g_rowptr[Nn];
__device__ int g_col[Ee];
__device__ int g_rank[Ee];
__device__ int g_total;

// ---- packed f32x2 helpers (sm_103a FFMA2) ----
__device__ __forceinline__ uint64_t pk2(float lo, float hi) {
    uint64_t r; asm("mov.b64 %0, {%1,%2};" : "=l"(r) : "f"(lo), "f"(hi)); return r;
}
__device__ __forceinline__ void fma2(uint64_t& acc, uint64_t a, uint64_t b) {
    asm("fma.rn.f32x2 %0, %1, %2, %0;" : "+l"(acc) : "l"(a), "l"(b));
}
__device__ __forceinline__ float2 upk(uint64_t v) {
    float2 r; asm("mov.b64 {%0,%1}, %2;" : "=f"(r.x), "=f"(r.y) : "l"(v)); return r;
}

// ---------------- setup: zero CSR counters + proj P + combined round-1 weights ----------------
// blocks 0..78 : zero g_deg / g_total
// block 79     : g_P = reshape(W_gat) @ [a_l | a_r]   (512 outputs)
// blocks 80..122: combined weights, 256 outputs each (10824 total).
//   Blocks whose output range touches P1/bp1 (idx >= 10560) recompute P locally
//   into shared memory (cheap: 512 x 64 MACs over 256 threads) -- no cross-block dep.
__global__ void setup_k(const float* __restrict__ W_enc, const float* __restrict__ b_enc,
                        const float* __restrict__ W_gat, const float* __restrict__ W_res,
                        const float* __restrict__ b_res,
                        const float* __restrict__ a_l, const float* __restrict__ a_r) {
    int t = threadIdx.x;
    int blk = blockIdx.x;
    if (blk < 79) {
        int idx = blk * 256 + t;
        if (idx < Nn) g_deg[idx] = 0;
        if (idx == 0) g_total = 0;
        return;
    }
    if (blk == 79) {
        // proj: 512 outputs
        for (int i = t; i < HIDD*8; i += 256) {
            int k = i >> 3, q = i & 7;
            int h = q & 3;
            const float* a = (q < 4) ? a_l : a_r;
            float s = 0.f;
#pragma unroll
            for (int d = 0; d < HIDD; d++)
                s += W_gat[k*FTC + h*HIDD + d] * a[h*HIDD + d];
            g_P[i] = s;
        }
        return;
    }
    // comb blocks: 256 outputs each
    int base = (blk - 80) * 256;
    __shared__ float Psh[HIDD*8];
    if (base + 255 >= 10560) {
        // this block needs P: recompute locally (2 iters/thread)
        for (int i = t; i < HIDD*8; i += 256) {
            int k = i >> 3, q = i & 7;
            int h = q & 3;
            const float* a = (q < 4) ? a_l : a_r;
            float s = 0.f;
#pragma unroll
            for (int d = 0; d < HIDD; d++)
                s += W_gat[k*FTC + h*HIDD + d] * a[h*HIDD + d];
            Psh[i] = s;
        }
        __syncthreads();
    }
    int idx = base + t;
    if (idx >= 10824) return;
    if (idx < 8192) {                       // Wg1[in][c]
        int in = idx >> 8, c = idx & 255;
        float s = 0.f;
#pragma unroll
        for (int k = 0; k < HIDD; k++) s += W_enc[in*HIDD + k] * W_gat[k*FTC + c];
        g_Wg1[in*FTC + c] = s;
    } else if (idx < 8448) {                // bg1[c]
        int c = idx - 8192;
        float s = 0.f;
#pragma unroll
        for (int k = 0; k < HIDD; k++) s += b_enc[k] * W_gat[k*FTC + c];
        g_bg1[c] = s;
    } else if (idx < 10496) {               // Wr1[in][c]
        int j = idx - 8448;
        int in = j >> 6, c = j & 63;
        float s = 0.f;
#pragma unroll
        for (int k = 0; k < HIDD; k++) s += W_enc[in*HIDD + k] * W_res[k*HIDD + c];
        g_Wr1[in*HIDD + c] = s;
    } else if (idx < 10560) {               // br1[c]
        int c = idx - 10496;
        float s = b_res[c];
#pragma unroll
        for (int k = 0; k < HIDD; k++) s += b_enc[k] * W_res[k*HIDD + c];
        g_br1[c] = s;
    } else if (idx < 10816) {               // P1[in][q]
        int j = idx - 10560;
        int in = j >> 3, q = j & 7;
        float s = 0.f;
#pragma unroll
        for (int k = 0; k < HIDD; k++) s += W_enc[in*HIDD + k] * Psh[k*8 + q];
        g_P1[in*8 + q] = s;
    } else {                                // bp1[q]
        int q = idx - 10816;
        float s = 0.f;
#pragma unroll
        for (int k = 0; k < HIDD; k++) s += b_enc[k] * Psh[k*8 + q];
        g_bp1[q] = s;
    }
}

// ---------------- CSR build ----------------
__global__ void hist_k(const int* __restrict__ ei) {
    int idx = blockIdx.x * blockDim.x + threadIdx.x;
    if (idx < Ee) g_rank[idx] = atomicAdd(&g_deg[ei[Ee + idx]], 1);
}

__global__ void alloc_k() {
    int idx = blockIdx.x * blockDim.x + threadIdx.x;
    int lane = threadIdx.x & 31;
    int d = (idx < Nn) ? g_deg[idx] : 0;
    int incl = d;
#pragma unroll
    for (int o = 1; o < 32; o <<= 1) {
        int t = __shfl_up_sync(0xffffffffu, incl, o);
        if (lane >= o) incl += t;
    }
    int wtot = __shfl_sync(0xffffffffu, incl, 31);
    int base = 0;
    if (lane == 0) base = atomicAdd(&g_total, wtot);
    base = __shfl_sync(0xffffffffu, base, 0);
    if (idx < Nn) g_rowptr[idx] = base + incl - d;
}

__global__ void fill_k(const int* __restrict__ ei) {
    int idx = blockIdx.x * blockDim.x + threadIdx.x;
    if (idx >= Ee) return;
    int d = ei[Ee + idx];
    g_col[g_rowptr[d] + g_rank[idx]] = ei[idx];
}

// ---------------- ft/res/el/er from either h (round 1, K=32) or g_x (round 2, K=64) ----------------
#define FTROWS 32
#define XPAD 17             // u64 pitch (pad)
__global__ void ft_k(const float* __restrict__ h,
                     const float* __restrict__ W_gat,
                     const float* __restrict__ W_res, const float* __restrict__ b_res,
                     int round1) {
    __shared__ uint64_t xs2[HIDD * XPAD];
    __shared__ float Ps[HIDD * 8];
    int t = threadIdx.x;
    int nb0 = blockIdx.x * FTROWS;

    const float* Wg = round1 ? g_Wg1 : W_gat;
    const float* bg = round1 ? g_bg1 : g_zeros;
    const float* Wr = round1 ? g_Wr1 : W_res;
    const float* br = round1 ? g_br1 : b_res;
    const float* Pm = round1 ? g_P1  : g_P;
    const float* bp = round1 ? g_bp1 : g_zeros;
    const int K = round1 ? INF_DIM : HIDD;

    // load source transposed row-paired into smem
    {
        float* xf = (float*)xs2;
        if (round1) {
            for (int i = t; i < FTROWS*INF_DIM; i += 256) {
                int row = i >> 5, k = i & 31;
                int nbrow = nb0 + row;
                int n = nbrow >> 1, b = nbrow & 1;
                xf[k*(2*XPAD) + row] = h[((size_t)b*Nn + n)*INF_DIM + k];
            }
        } else {
            for (int i = t; i < FTROWS*HIDD; i += 256) {
                int row = i >> 6, k = i & 63;
                xf[k*(2*XPAD) + row] = g_x[(size_t)(nb0 + row)*HIDD + k];
            }
        }
        for (int i = t; i < K*8; i += 256) Ps[i] = Pm[i];
    }
    __syncthreads();

    // main GEMM: col-quad x 4 row-pairs (1 LDG.128 + 4 LDS.64 + 16 FFMA2 per k)
    {
        int cq = t & 63;
        int rh = t >> 6;
        uint64_t acc[4][4];
#pragma unroll
        for (int c = 0; c < 4; c++) {
            float bc = bg[cq*4 + c];
            uint64_t b2 = pk2(bc, bc);
#pragma unroll
            for (int r = 0; r < 4; r++) acc[c][r] = b2;
        }

        for (int k = 0; k < K; k++) {
            float4 w = *(const float4*)&Wg[k*FTC + cq*4];
            uint64_t w0 = pk2(w.x, w.x);
            uint64_t w1 = pk2(w.y, w.y);
            uint64_t w2 = pk2(w.z, w.z);
            uint64_t w3 = pk2(w.w, w.w);
            const uint64_t* xr = &xs2[k*XPAD + rh*4];
#pragma unroll
            for (int r = 0; r < 4; r++) {
                uint64_t xv = xr[r];
                fma2(acc[0][r], xv, w0);
                fma2(acc[1][r], xv, w1);
                fma2(acc[2][r], xv, w2);
                fma2(acc[3][r], xv, w3);
            }
        }
#pragma unroll
        for (int r = 0; r < 4; r++) {
            float2 v0 = upk(acc[0][r]);
            float2 v1 = upk(acc[1][r]);
            float2 v2 = upk(acc[2][r]);
            float2 v3 = upk(acc[3][r]);
            int rp = rh*4 + r;
            __half2 e0 = __floats2half2_rn(v0.x, v1.x);
            __half2 e1 = __floats2half2_rn(v2.x, v3.x);
            __half2 o0 = __floats2half2_rn(v0.y, v1.y);
            __half2 o1 = __floats2half2_rn(v2.y, v3.y);
            *(uint2*)&g_fth[((size_t)(nb0 + 2*rp))*FTC + cq*4]     = make_uint2(
                *(unsigned*)&e0, *(unsigned*)&e1);
            *(uint2*)&g_fth[((size_t)(nb0 + 2*rp + 1))*FTC + cq*4] = make_uint2(
                *(unsigned*)&o0, *(unsigned*)&o1);
        }
    }

    // res: thread owns col pair (2cr, 2cr+1), 2 row-pairs
    {
        int cr = t & 31;
        int rr = t >> 5;
        float2 bb = *(const float2*)&br[cr*2];
        uint64_t a0[2], a1[2];
        a0[0] = pk2(bb.x, bb.x); a0[1] = a0[0];
        a1[0] = pk2(bb.y, bb.y); a1[1] = a1[0];
        for (int k = 0; k < K; k++) {
            float2 w = *(const float2*)&Wr[k*HIDD + cr*2];
            uint64_t w0 = pk2(w.x, w.x);
            uint64_t w1 = pk2(w.y, w.y);
            const uint64_t* xr = &xs2[k*XPAD + rr*2];
            fma2(a0[0], xr[0], w0); fma2(a1[0], xr[0], w1);
            fma2(a0[1], xr[1], w0); fma2(a1[1], xr[1], w1);
        }
#pragma unroll
        for (int i = 0; i < 2; i++) {
            float2 va = upk(a0[i]);
            float2 vb = upk(a1[i]);
            int rp = rr*2 + i;
            *(float2*)&g_res[(size_t)(nb0 + 2*rp)*HIDD + cr*2]     = make_float2(va.x, vb.x);
            *(float2*)&g_res[(size_t)(nb0 + 2*rp + 1)*HIDD + cr*2] = make_float2(va.y, vb.y);
        }
    }

    // el/er
    {
        int r = t >> 3, q = t & 7;
        const float* xf = (const float*)xs2;
        float s = bp[q];
        for (int k = 0; k < K; k++)
            s += xf[k*(2*XPAD) + r] * Ps[k*8 + q];
        int nb = nb0 + r;
        if (q < 4) g_el[nb*4 + q]       = s;
        else       g_er[nb*4 + (q - 4)] = s;
    }
}

// ---------------- fused node-centric GAT aggregation + update (+ optional decoder) ----------------
// EXACT R11 structure (best known): one warp per dst node, both batches;
// e-values batched per 32-edge window; simple per-edge break in the FMA loop.
__global__ void node_agg_k(const float* __restrict__ b_gat,
                           const float* __restrict__ W_dec, const float* __restrict__ b_dec,
                           float* __restrict__ out, int last) {
    int w = (blockIdx.x * blockDim.x + threadIdx.x) >> 5;
    int lane = threadIdx.x & 31;
    if (w >= Nn) return;
    int beg = g_rowptr[w];
    int end = beg + g_deg[w];

    int slot = lane >> 3;              // e-role: edge sub-slot (0..3)
    int bh   = lane & 7;               // e-role: (b,h)
    int b    = lane >> 4;              // gather role: batch
    int l16  = lane & 15;              // gather role: dim-quad

    float er_v = (lane < 8) ? g_er[w*8 + lane] : 0.f;
    float er_mine = __shfl_sync(0xffffffffu, er_v, bh);

    float zpart = 0.f;
    float4 acc[HEADS];
#pragma unroll
    for (int h = 0; h < HEADS; h++) acc[h] = make_float4(0.f, 0.f, 0.f, 0.f);

    for (int i0 = beg; i0 < end; i0 += 32) {
        int nE = end - i0; if (nE > 32) nE = 32;
        int sj = (i0 + lane < end) ? g_col[i0 + lane] : 0;

        // batch e-values: lane handles edges j = slot + 4k, its own bh
        float ereg[8];
#pragma unroll
        for (int k = 0; k < 8; k++) {
            int j = slot + 4*k;
            int s = __shfl_sync(0xffffffffu, sj, j);
            float e = 0.f;
            if (j < nE) {
                float v = g_el[s*8 + bh] + er_mine;
                v = v > 0.f ? v : SLOPE * v;
                e = __expf(v);
            }
            ereg[k] = e;
            zpart += e;
        }

        // FMA loop: pure shfl + coalesced fp16 gather + FMA
#pragma unroll
        for (int j = 0; j < 32; j++) {
            if (j >= nE) break;
            const int kk = j >> 2, sl2 = j & 3;
            int s = __shfl_sync(0xffffffffu, sj, j);
            float a0 = __shfl_sync(0xffffffffu, ereg[kk], sl2*8 + b*4 + 0);
            float a1 = __shfl_sync(0xffffffffu, ereg[kk], sl2*8 + b*4 + 1);
            float a2 = __shfl_sync(0xffffffffu, ereg[kk], sl2*8 + b*4 + 2);
            float a3 = __shfl_sync(0xffffffffu, ereg[kk], sl2*8 + b*4 + 3);
            const uint2* f = (const uint2*)&g_fth[((size_t)(s*2 + b))*FTC];
            uint2 u0 = f[l16];
            uint2 u1 = f[16 + l16];
            uint2 u2 = f[32 + l16];
            uint2 u3 = f[48 + l16];
            float2 p, q;
            p = __half22float2(*(__half2*)&u0.x); q = __half22float2(*(__half2*)&u0.y);
            acc[0].x += a0*p.x; acc[0].y += a0*p.y; acc[0].z += a0*q.x; acc[0].w += a0*q.y;
            p = __half22float2(*(__half2*)&u1.x); q = __half22float2(*(__half2*)&u1.y);
            acc[1].x += a1*p.x; acc[1].y += a1*p.y; acc[1].z += a1*q.x; acc[1].w += a1*q.y;
            p = __half22float2(*(__half2*)&u2.x); q = __half22float2(*(__half2*)&u2.y);
            acc[2].x += a2*p.x; acc[2].y += a2*p.y; acc[2].z += a2*q.x; acc[2].w += a2*q.y;
            p = __half22float2(*(__half2*)&u3.x); q = __half22float2(*(__half2*)&u3.y);
            acc[3].x += a3*p.x; acc[3].y += a3*p.y; acc[3].z += a3*q.x; acc[3].w += a3*q.y;
        }
    }

    // z reduce: sum over the 4 edge sub-slots -> lane holds z for its bh
    zpart += __shfl_xor_sync(0xffffffffu, zpart, 8);
    zpart += __shfl_xor_sync(0xffffffffu, zpart, 16);

    // normalize + head-mean
    float4 o = make_float4(0.f, 0.f, 0.f, 0.f);
#pragma unroll
    for (int h = 0; h < HEADS; h++) {
        float zh = __shfl_sync(0xffffffffu, zpart, b*4 + h);
        float rz = (zh > 0.f) ? 0.25f / zh : 0.f;
        o.x += acc[h].x * rz; o.y += acc[h].y * rz;
        o.z += acc[h].z * rz; o.w += acc[h].w * rz;
    }

    // epilogue: + mean_h(b_gat) + res, ELU
    int d0 = l16 * 4;
    const float4* bg = (const float4*)b_gat;
    float4 b0 = bg[l16], b1 = bg[16 + l16], b2 = bg[32 + l16], b3 = bg[48 + l16];
    float4 bgm;
    bgm.x = 0.25f*(b0.x + b1.x + b2.x + b3.x);
    bgm.y = 0.25f*(b0.y + b1.y + b2.y + b3.y);
    bgm.z = 0.25f*(b0.z + b1.z + b2.z + b3.z);
    bgm.w = 0.25f*(b0.w + b1.w + b2.w + b3.w);

    float4 rv = *(const float4*)&g_res[((size_t)(w*2 + b))*HIDD + d0];
    float ox = o.x + bgm.x + rv.x;
    float oy = o.y + bgm.y + rv.y;
    float oz = o.z + bgm.z + rv.z;
    float ow = o.w + bgm.w + rv.w;
    ox = ox > 0.f ? ox : expm1f(ox);
    oy = oy > 0.f ? oy : expm1f(oy);
    oz = oz > 0.f ? oz : expm1f(oz);
    ow = ow > 0.f ? ow : expm1f(ow);

    if (!last) {
        *(float4*)&g_x[((size_t)(w*2 + b))*HIDD + d0] = make_float4(ox, oy, oz, ow);
    } else {
        // fused decoder: out[b, w, :] = x[w, b, :] @ W_dec + b_dec
        float po[OUTD];
        const float4* W0 = (const float4*)&W_dec[(d0 + 0)*OUTD];
        const float4* W1 = (const float4*)&W_dec[(d0 + 1)*OUTD];
        const float4* W2 = (const float4*)&W_dec[(d0 + 2)*OUTD];
        const float4* W3 = (const float4*)&W_dec[(d0 + 3)*OUTD];
        float4 wa, wb;
        wa = W0[0]; wb = W0[1];
        po[0] = ox*wa.x; po[1] = ox*wa.y; po[2] = ox*wa.z; po[3] = ox*wa.w;
        po[4] = ox*wb.x; po[5] = ox*wb.y; po[6] = ox*wb.z; po[7] = ox*wb.w;
        wa = W1[0]; wb = W1[1];
        po[0] += oy*wa.x; po[1] += oy*wa.y; po[2] += oy*wa.z; po[3] += oy*wa.w;
        po[4] += oy*wb.x; po[5] += oy*wb.y; po[6] += oy*wb.z; po[7] += oy*wb.w;
        wa = W2[0]; wb = W2[1];
        po[0] += oz*wa.x; po[1] += oz*wa.y; po[2] += oz*wa.z; po[3] += oz*wa.w;
        po[4] += oz*wb.x; po[5] += oz*wb.y; po[6] += oz*wb.z; po[7] += oz*wb.w;
        wa = W3[0]; wb = W3[1];
        po[0] += ow*wa.x; po[1] += ow*wa.y; po[2] += ow*wa.z; po[3] += ow*wa.w;
        po[4] += ow*wb.x; po[5] += ow*wb.y; po[6] += ow*wb.z; po[7] += ow*wb.w;
#pragma unroll
        for (int off = 1; off < 16; off <<= 1)
#pragma unroll
            for (int oo = 0; oo < OUTD; oo++)
                po[oo] += __shfl_xor_sync(0xffffffffu, po[oo], off);
        if (l16 == 0) {
            float* op = &out[((size_t)b*Nn + w)*OUTD];
            float4 v0 = make_float4(po[0] + b_dec[0], po[1] + b_dec[1],
                                    po[2] + b_dec[2], po[3] + b_dec[3]);
            float4 v1 = make_float4(po[4] + b_dec[4], po[5] + b_dec[5],
                                    po[6] + b_dec[6], po[7] + b_dec[7]);
            *(float4*)&op[0] = v0;
            *(float4*)&op[4] = v1;
        }
    }
}

extern "C" void kernel_launch(void* const* d_in, const int* in_sizes, int n_in,
                              void* d_out, int out_size) {
    const float* h     = (const float*)d_in[0];
    const int*   ei    = (const int*)  d_in[1];
    const float* W_enc = (const float*)d_in[2];
    const float* b_enc = (const float*)d_in[3];
    const float* W_gat = (const float*)d_in[4];
    const float* a_l   = (const float*)d_in[5];
    const float* a_r   = (const float*)d_in[6];
    const float* b_gat = (const float*)d_in[7];
    const float* W_res = (const float*)d_in[8];
    const float* b_res = (const float*)d_in[9];
    const float* W_dec = (const float*)d_in[10];
    const float* b_dec = (const float*)d_in[11];
    float* out = (float*)d_out;

    // setup: zero CSR counters + P + combined round-1 weights (1 kernel, 123 parallel blocks)
    setup_k<<<123, 256>>>(W_enc, b_enc, W_gat, W_res, b_res, a_l, a_r);
    // CSR build
    hist_k<<<(Ee + 255)/256, 256>>>(ei);
    alloc_k<<<(Nn + 255)/256, 256>>>();
    fill_k<<<(Ee + 255)/256, 256>>>(ei);

    for (int it = 0; it < 2; ++it) {
        ft_k<<<NB/FTROWS, 256>>>(h, W_gat, W_res, b_res, it == 0);
        node_agg_k<<<(Nn*32 + 255)/256, 256>>>(b_gat, W_dec, b_dec, out, it == 1);
    }
}

// round 17
// speedup vs baseline: 1.2022x; 1.0289x over previous
#include <cuda_runtime.h>
#include <cuda_fp16.h>
#include <cstdint>

// Problem constants
#define Nn 20000
#define Ee 320000
#define Bb 2
#define INF_DIM 32
#define HIDD 64
#define HEADS 4
#define OUTD 8
#define SLOPE 0.2f

#define NB (Nn*Bb)              // 40000
#define FTC (HEADS*HIDD)        // 256

// Scratch (device globals)
__device__ __align__(16) float g_x[NB*HIDD];
__device__ __align__(16) __half g_fth[(size_t)NB*FTC];   // ft in fp16
__device__ __align__(16) float g_res[NB*HIDD];
__device__ float g_el[NB*HEADS];   // [(node*2+b)*4 + h]
__device__ float g_er[NB*HEADS];
__device__ float g_P[HIDD*8];      // [k*8 + q], q<4: Pl, q>=4: Pr
// round-1 combined (encoder-folded) weights
__device__ __align__(16) float g_Wg1[INF_DIM*FTC];
__device__ float g_bg1[FTC];
__device__ __align__(16) float g_Wr1[INF_DIM*HIDD];
__device__ float g_br1[HIDD];
__device__ float g_P1[INF_DIM*8];
__device__ float g_bp1[8];
__device__ float g_zeros[FTC];     // never written: stays zero
__device__ int g_deg[Nn];
__device__ int g_rowptr[Nn];
__device__ int g_col[Ee];
__device__ int g_rank[Ee];
__device__ int g_total;

// ---- packed f32x2 helpers (sm_103a FFMA2) ----
__device__ __forceinline__ uint64_t pk2(float lo, float hi) {
    uint64_t r; asm("mov.b64 %0, {%1,%2};" : "=l"(r) : "f"(lo), "f"(hi)); return r;
}
__device__ __forceinline__ void fma2(uint64_t& acc, uint64_t a, uint64_t b) {
    asm("fma.rn.f32x2 %0, %1, %2, %0;" : "+l"(acc) : "l"(a), "l"(b));
}
__device__ __forceinline__ float2 upk(uint64_t v) {
    float2 r; asm("mov.b64 {%0,%1}, %2;" : "=f"(r.x), "=f"(r.y) : "l"(v)); return r;
}

// ---------------- setup: zero CSR counters + proj P + combined round-1 weights ----------------
__global__ void setup_k(const float* __restrict__ W_enc, const float* __restrict__ b_enc,
                        const float* __restrict__ W_gat, const float* __restrict__ W_res,
                        const float* __restrict__ b_res,
                        const float* __restrict__ a_l, const float* __restrict__ a_r) {
    int t = threadIdx.x;
    int blk = blockIdx.x;
    if (blk < 79) {
        int idx = blk * 256 + t;
        if (idx < Nn) g_deg[idx] = 0;
        if (idx == 0) g_total = 0;
        return;
    }
    if (blk == 79) {
        for (int i = t; i < HIDD*8; i += 256) {
            int k = i >> 3, q = i & 7;
            int h = q & 3;
            const float* a = (q < 4) ? a_l : a_r;
            float s = 0.f;
#pragma unroll
            for (int d = 0; d < HIDD; d++)
                s += W_gat[k*FTC + h*HIDD + d] * a[h*HIDD + d];
            g_P[i] = s;
        }
        return;
    }
    int base = (blk - 80) * 256;
    __shared__ float Psh[HIDD*8];
    if (base + 255 >= 10560) {
        for (int i = t; i < HIDD*8; i += 256) {
            int k = i >> 3, q = i & 7;
            int h = q & 3;
            const float* a = (q < 4) ? a_l : a_r;
            float s = 0.f;
#pragma unroll
            for (int d = 0; d < HIDD; d++)
                s += W_gat[k*FTC + h*HIDD + d] * a[h*HIDD + d];
            Psh[i] = s;
        }
        __syncthreads();
    }
    int idx = base + t;
    if (idx >= 10824) return;
    if (idx < 8192) {
        int in = idx >> 8, c = idx & 255;
        float s = 0.f;
#pragma unroll
        for (int k = 0; k < HIDD; k++) s += W_enc[in*HIDD + k] * W_gat[k*FTC + c];
        g_Wg1[in*FTC + c] = s;
    } else if (idx < 8448) {
        int c = idx - 8192;
        float s = 0.f;
#pragma unroll
        for (int k = 0; k < HIDD; k++) s += b_enc[k] * W_gat[k*FTC + c];
        g_bg1[c] = s;
    } else if (idx < 10496) {
        int j = idx - 8448;
        int in = j >> 6, c = j & 63;
        float s = 0.f;
#pragma unroll
        for (int k = 0; k < HIDD; k++) s += W_enc[in*HIDD + k] * W_res[k*HIDD + c];
        g_Wr1[in*HIDD + c] = s;
    } else if (idx < 10560) {
        int c = idx - 10496;
        float s = b_res[c];
#pragma unroll
        for (int k = 0; k < HIDD; k++) s += b_enc[k] * W_res[k*HIDD + c];
        g_br1[c] = s;
    } else if (idx < 10816) {
        int j = idx - 10560;
        int in = j >> 3, q = j & 7;
        float s = 0.f;
#pragma unroll
        for (int k = 0; k < HIDD; k++) s += W_enc[in*HIDD + k] * Psh[k*8 + q];
        g_P1[in*8 + q] = s;
    } else {
        int q = idx - 10816;
        float s = 0.f;
#pragma unroll
        for (int k = 0; k < HIDD; k++) s += b_enc[k] * Psh[k*8 + q];
        g_bp1[q] = s;
    }
}

// ---------------- CSR build ----------------
__global__ void hist_k(const int* __restrict__ ei) {
    int idx = blockIdx.x * blockDim.x + threadIdx.x;
    if (idx < Ee) g_rank[idx] = atomicAdd(&g_deg[ei[Ee + idx]], 1);
}

__global__ void alloc_k() {
    int idx = blockIdx.x * blockDim.x + threadIdx.x;
    int lane = threadIdx.x & 31;
    int d = (idx < Nn) ? g_deg[idx] : 0;
    int incl = d;
#pragma unroll
    for (int o = 1; o < 32; o <<= 1) {
        int t = __shfl_up_sync(0xffffffffu, incl, o);
        if (lane >= o) incl += t;
    }
    int wtot = __shfl_sync(0xffffffffu, incl, 31);
    int base = 0;
    if (lane == 0) base = atomicAdd(&g_total, wtot);
    base = __shfl_sync(0xffffffffu, base, 0);
    if (idx < Nn) g_rowptr[idx] = base + incl - d;
}

__global__ void fill_k(const int* __restrict__ ei) {
    int idx = blockIdx.x * blockDim.x + threadIdx.x;
    if (idx >= Ee) return;
    int d = ei[Ee + idx];
    g_col[g_rowptr[d] + g_rank[idx]] = ei[idx];
}

// ---------------- ft/res/el/er from either h (round 1, K=32) or g_x (round 2, K=64) ----------------
#define FTROWS 32
#define XPAD 17             // u64 pitch (pad)
__global__ void ft_k(const float* __restrict__ h,
                     const float* __restrict__ W_gat,
                     const float* __restrict__ W_res, const float* __restrict__ b_res,
                     int round1) {
    __shared__ uint64_t xs2[HIDD * XPAD];
    __shared__ float Ps[HIDD * 8];
    int t = threadIdx.x;
    int nb0 = blockIdx.x * FTROWS;

    const float* Wg = round1 ? g_Wg1 : W_gat;
    const float* bg = round1 ? g_bg1 : g_zeros;
    const float* Wr = round1 ? g_Wr1 : W_res;
    const float* br = round1 ? g_br1 : b_res;
    const float* Pm = round1 ? g_P1  : g_P;
    const float* bp = round1 ? g_bp1 : g_zeros;
    const int K = round1 ? INF_DIM : HIDD;

    {
        float* xf = (float*)xs2;
        if (round1) {
            for (int i = t; i < FTROWS*INF_DIM; i += 256) {
                int row = i >> 5, k = i & 31;
                int nbrow = nb0 + row;
                int n = nbrow >> 1, b = nbrow & 1;
                xf[k*(2*XPAD) + row] = h[((size_t)b*Nn + n)*INF_DIM + k];
            }
        } else {
            for (int i = t; i < FTROWS*HIDD; i += 256) {
                int row = i >> 6, k = i & 63;
                xf[k*(2*XPAD) + row] = g_x[(size_t)(nb0 + row)*HIDD + k];
            }
        }
        for (int i = t; i < K*8; i += 256) Ps[i] = Pm[i];
    }
    __syncthreads();

    // main GEMM: col-quad x 4 row-pairs (1 LDG.128 + 4 LDS.64 + 16 FFMA2 per k)
    {
        int cq = t & 63;
        int rh = t >> 6;
        uint64_t acc[4][4];
#pragma unroll
        for (int c = 0; c < 4; c++) {
            float bc = bg[cq*4 + c];
            uint64_t b2 = pk2(bc, bc);
#pragma unroll
            for (int r = 0; r < 4; r++) acc[c][r] = b2;
        }

        for (int k = 0; k < K; k++) {
            float4 w = *(const float4*)&Wg[k*FTC + cq*4];
            uint64_t w0 = pk2(w.x, w.x);
            uint64_t w1 = pk2(w.y, w.y);
            uint64_t w2 = pk2(w.z, w.z);
            uint64_t w3 = pk2(w.w, w.w);
            const uint64_t* xr = &xs2[k*XPAD + rh*4];
#pragma unroll
            for (int r = 0; r < 4; r++) {
                uint64_t xv = xr[r];
                fma2(acc[0][r], xv, w0);
                fma2(acc[1][r], xv, w1);
                fma2(acc[2][r], xv, w2);
                fma2(acc[3][r], xv, w3);
            }
        }
#pragma unroll
        for (int r = 0; r < 4; r++) {
            float2 v0 = upk(acc[0][r]);
            float2 v1 = upk(acc[1][r]);
            float2 v2 = upk(acc[2][r]);
            float2 v3 = upk(acc[3][r]);
            int rp = rh*4 + r;
            __half2 e0 = __floats2half2_rn(v0.x, v1.x);
            __half2 e1 = __floats2half2_rn(v2.x, v3.x);
            __half2 o0 = __floats2half2_rn(v0.y, v1.y);
            __half2 o1 = __floats2half2_rn(v2.y, v3.y);
            *(uint2*)&g_fth[((size_t)(nb0 + 2*rp))*FTC + cq*4]     = make_uint2(
                *(unsigned*)&e0, *(unsigned*)&e1);
            *(uint2*)&g_fth[((size_t)(nb0 + 2*rp + 1))*FTC + cq*4] = make_uint2(
                *(unsigned*)&o0, *(unsigned*)&o1);
        }
    }

    // res: thread owns col pair (2cr, 2cr+1), 2 row-pairs
    {
        int cr = t & 31;
        int rr = t >> 5;
        float2 bb = *(const float2*)&br[cr*2];
        uint64_t a0[2], a1[2];
        a0[0] = pk2(bb.x, bb.x); a0[1] = a0[0];
        a1[0] = pk2(bb.y, bb.y); a1[1] = a1[0];
        for (int k = 0; k < K; k++) {
            float2 w = *(const float2*)&Wr[k*HIDD + cr*2];
            uint64_t w0 = pk2(w.x, w.x);
            uint64_t w1 = pk2(w.y, w.y);
            const uint64_t* xr = &xs2[k*XPAD + rr*2];
            fma2(a0[0], xr[0], w0); fma2(a1[0], xr[0], w1);
            fma2(a0[1], xr[1], w0); fma2(a1[1], xr[1], w1);
        }
#pragma unroll
        for (int i = 0; i < 2; i++) {
            float2 va = upk(a0[i]);
            float2 vb = upk(a1[i]);
            int rp = rr*2 + i;
            *(float2*)&g_res[(size_t)(nb0 + 2*rp)*HIDD + cr*2]     = make_float2(va.x, vb.x);
            *(float2*)&g_res[(size_t)(nb0 + 2*rp + 1)*HIDD + cr*2] = make_float2(va.y, vb.y);
        }
    }

    // el/er
    {
        int r = t >> 3, q = t & 7;
        const float* xf = (const float*)xs2;
        float s = bp[q];
        for (int k = 0; k < K; k++)
            s += xf[k*(2*XPAD) + r] * Ps[k*8 + q];
        int nb = nb0 + r;
        if (q < 4) g_el[nb*4 + q]       = s;
        else       g_er[nb*4 + (q - 4)] = s;
    }
}

// ---------------- fused node-centric GAT aggregation + update (+ optional decoder) ----------------
// EXACT R11 structure (best known): one warp per dst node, both batches;
// e-values batched per 32-edge window; simple per-edge break in the FMA loop.
__global__ void node_agg_k(const float* __restrict__ b_gat,
                           const float* __restrict__ W_dec, const float* __restrict__ b_dec,
                           float* __restrict__ out, int last) {
    int w = (blockIdx.x * blockDim.x + threadIdx.x) >> 5;
    int lane = threadIdx.x & 31;
    if (w >= Nn) return;
    int beg = g_rowptr[w];
    int end = beg + g_deg[w];

    int slot = lane >> 3;              // e-role: edge sub-slot (0..3)
    int bh   = lane & 7;               // e-role: (b,h)
    int b    = lane >> 4;              // gather role: batch
    int l16  = lane & 15;              // gather role: dim-quad

    float er_v = (lane < 8) ? g_er[w*8 + lane] : 0.f;
    float er_mine = __shfl_sync(0xffffffffu, er_v, bh);

    float zpart = 0.f;
    float4 acc[HEADS];
#pragma unroll
    for (int h = 0; h < HEADS; h++) acc[h] = make_float4(0.f, 0.f, 0.f, 0.f);

    for (int i0 = beg; i0 < end; i0 += 32) {
        int nE = end - i0; if (nE > 32) nE = 32;
        int sj = (i0 + lane < end) ? g_col[i0 + lane] : 0;

        // batch e-values: lane handles edges j = slot + 4k, its own bh
        float ereg[8];
#pragma unroll
        for (int k = 0; k < 8; k++) {
            int j = slot + 4*k;
            int s = __shfl_sync(0xffffffffu, sj, j);
            float e = 0.f;
            if (j < nE) {
                float v = g_el[s*8 + bh] + er_mine;
                v = v > 0.f ? v : SLOPE * v;
                e = __expf(v);
            }
            ereg[k] = e;
            zpart += e;
        }

        // FMA loop: pure shfl + coalesced fp16 gather + FMA
#pragma unroll
        for (int j = 0; j < 32; j++) {
            if (j >= nE) break;
            const int kk = j >> 2, sl2 = j & 3;
            int s = __shfl_sync(0xffffffffu, sj, j);
            float a0 = __shfl_sync(0xffffffffu, ereg[kk], sl2*8 + b*4 + 0);
            float a1 = __shfl_sync(0xffffffffu, ereg[kk], sl2*8 + b*4 + 1);
            float a2 = __shfl_sync(0xffffffffu, ereg[kk], sl2*8 + b*4 + 2);
            float a3 = __shfl_sync(0xffffffffu, ereg[kk], sl2*8 + b*4 + 3);
            const uint2* f = (const uint2*)&g_fth[((size_t)(s*2 + b))*FTC];
            uint2 u0 = f[l16];
            uint2 u1 = f[16 + l16];
            uint2 u2 = f[32 + l16];
            uint2 u3 = f[48 + l16];
            float2 p, q;
            p = __half22float2(*(__half2*)&u0.x); q = __half22float2(*(__half2*)&u0.y);
            acc[0].x += a0*p.x; acc[0].y += a0*p.y; acc[0].z += a0*q.x; acc[0].w += a0*q.y;
            p = __half22float2(*(__half2*)&u1.x); q = __half22float2(*(__half2*)&u1.y);
            acc[1].x += a1*p.x; acc[1].y += a1*p.y; acc[1].z += a1*q.x; acc[1].w += a1*q.y;
            p = __half22float2(*(__half2*)&u2.x); q = __half22float2(*(__half2*)&u2.y);
            acc[2].x += a2*p.x; acc[2].y += a2*p.y; acc[2].z += a2*q.x; acc[2].w += a2*q.y;
            p = __half22float2(*(__half2*)&u3.x); q = __half22float2(*(__half2*)&u3.y);
            acc[3].x += a3*p.x; acc[3].y += a3*p.y; acc[3].z += a3*q.x; acc[3].w += a3*q.y;
        }
    }

    // z reduce: sum over the 4 edge sub-slots -> lane holds z for its bh
    zpart += __shfl_xor_sync(0xffffffffu, zpart, 8);
    zpart += __shfl_xor_sync(0xffffffffu, zpart, 16);

    // normalize + head-mean
    float4 o = make_float4(0.f, 0.f, 0.f, 0.f);
#pragma unroll
    for (int h = 0; h < HEADS; h++) {
        float zh = __shfl_sync(0xffffffffu, zpart, b*4 + h);
        float rz = (zh > 0.f) ? 0.25f / zh : 0.f;
        o.x += acc[h].x * rz; o.y += acc[h].y * rz;
        o.z += acc[h].z * rz; o.w += acc[h].w * rz;
    }

    // epilogue: + mean_h(b_gat) + res, ELU
    int d0 = l16 * 4;
    const float4* bg = (const float4*)b_gat;
    float4 b0 = bg[l16], b1 = bg[16 + l16], b2 = bg[32 + l16], b3 = bg[48 + l16];
    float4 bgm;
    bgm.x = 0.25f*(b0.x + b1.x + b2.x + b3.x);
    bgm.y = 0.25f*(b0.y + b1.y + b2.y + b3.y);
    bgm.z = 0.25f*(b0.z + b1.z + b2.z + b3.z);
    bgm.w = 0.25f*(b0.w + b1.w + b2.w + b3.w);

    float4 rv = *(const float4*)&g_res[((size_t)(w*2 + b))*HIDD + d0];
    float ox = o.x + bgm.x + rv.x;
    float oy = o.y + bgm.y + rv.y;
    float oz = o.z + bgm.z + rv.z;
    float ow = o.w + bgm.w + rv.w;
    ox = ox > 0.f ? ox : expm1f(ox);
    oy = oy > 0.f ? oy : expm1f(oy);
    oz = oz > 0.f ? oz : expm1f(oz);
    ow = ow > 0.f ? ow : expm1f(ow);

    if (!last) {
        *(float4*)&g_x[((size_t)(w*2 + b))*HIDD + d0] = make_float4(ox, oy, oz, ow);
    } else {
        // fused decoder: out[b, w, :] = x[w, b, :] @ W_dec + b_dec
        float po[OUTD];
        const float4* W0 = (const float4*)&W_dec[(d0 + 0)*OUTD];
        const float4* W1 = (const float4*)&W_dec[(d0 + 1)*OUTD];
        const float4* W2 = (const float4*)&W_dec[(d0 + 2)*OUTD];
        const float4* W3 = (const float4*)&W_dec[(d0 + 3)*OUTD];
        float4 wa, wb;
        wa = W0[0]; wb = W0[1];
        po[0] = ox*wa.x; po[1] = ox*wa.y; po[2] = ox*wa.z; po[3] = ox*wa.w;
        po[4] = ox*wb.x; po[5] = ox*wb.y; po[6] = ox*wb.z; po[7] = ox*wb.w;
        wa = W1[0]; wb = W1[1];
        po[0] += oy*wa.x; po[1] += oy*wa.y; po[2] += oy*wa.z; po[3] += oy*wa.w;
        po[4] += oy*wb.x; po[5] += oy*wb.y; po[6] += oy*wb.z; po[7] += oy*wb.w;
        wa = W2[0]; wb = W2[1];
        po[0] += oz*wa.x; po[1] += oz*wa.y; po[2] += oz*wa.z; po[3] += oz*wa.w;
        po[4] += oz*wb.x; po[5] += oz*wb.y; po[6] += oz*wb.z; po[7] += oz*wb.w;
        wa = W3[0]; wb = W3[1];
        po[0] += ow*wa.x; po[1] += ow*wa.y; po[2] += ow*wa.z; po[3] += ow*wa.w;
        po[4] += ow*wb.x; po[5] += ow*wb.y; po[6] += ow*wb.z; po[7] += ow*wb.w;
#pragma unroll
        for (int off = 1; off < 16; off <<= 1)
#pragma unroll
            for (int oo = 0; oo < OUTD; oo++)
                po[oo] += __shfl_xor_sync(0xffffffffu, po[oo], off);
        if (l16 == 0) {
            float* op = &out[((size_t)b*Nn + w)*OUTD];
            float4 v0 = make_float4(po[0] + b_dec[0], po[1] + b_dec[1],
                                    po[2] + b_dec[2], po[3] + b_dec[3]);
            float4 v1 = make_float4(po[4] + b_dec[4], po[5] + b_dec[5],
                                    po[6] + b_dec[6], po[7] + b_dec[7]);
            *(float4*)&op[0] = v0;
            *(float4*)&op[4] = v1;
        }
    }
}

extern "C" void kernel_launch(void* const* d_in, const int* in_sizes, int n_in,
                              void* d_out, int out_size) {
    const float* h     = (const float*)d_in[0];
    const int*   ei    = (const int*)  d_in[1];
    const float* W_enc = (const float*)d_in[2];
    const float* b_enc = (const float*)d_in[3];
    const float* W_gat = (const float*)d_in[4];
    const float* a_l   = (const float*)d_in[5];
    const float* a_r   = (const float*)d_in[6];
    const float* b_gat = (const float*)d_in[7];
    const float* W_res = (const float*)d_in[8];
    const float* b_res = (const float*)d_in[9];
    const float* W_dec = (const float*)d_in[10];
    const float* b_dec = (const float*)d_in[11];
    float* out = (float*)d_out;

    // One-time host-side resources (streams/events: no device memory).
    static cudaStream_t s2 = nullptr;
    static cudaEvent_t evFork = nullptr, evJoin = nullptr;
    if (s2 == nullptr) {
        cudaStreamCreateWithFlags(&s2, cudaStreamNonBlocking);
        cudaEventCreateWithFlags(&evFork, cudaEventDisableTiming);
        cudaEventCreateWithFlags(&evJoin, cudaEventDisableTiming);
    }

    // setup: zero CSR counters + P + combined round-1 weights
    setup_k<<<123, 256>>>(W_enc, b_enc, W_gat, W_res, b_res, a_l, a_r);

    // fork: CSR build on s2 (depends only on setup's zeroing)
    cudaEventRecord(evFork, 0);
    cudaStreamWaitEvent(s2, evFork, 0);
    hist_k<<<(Ee + 255)/256, 256, 0, s2>>>(ei);
    alloc_k<<<(Nn + 255)/256, 256, 0, s2>>>();
    fill_k<<<(Ee + 255)/256, 256, 0, s2>>>(ei);
    cudaEventRecord(evJoin, s2);

    // main stream: round-1 ft (independent of CSR) overlaps with CSR build
    ft_k<<<NB/FTROWS, 256>>>(h, W_gat, W_res, b_res, 1);

    // join before aggregation
    cudaStreamWaitEvent(0, evJoin, 0);
    node_agg_k<<<(Nn*32 + 255)/256, 256>>>(b_gat, W_dec, b_dec, out, 0);

    // round 2
    ft_k<<<NB/FTROWS, 256>>>(h, W_gat, W_res, b_res, 0);
    node_agg_k<<<(Nn*32 + 255)/256, 256>>>(b_gat, W_dec, b_dec, out, 1);
}